// round 2
// baseline (speedup 1.0000x reference)
#include <cuda_runtime.h>
#include <cstdint>

// Double-precision global accumulator (scratch; no allocations allowed).
__device__ double g_mde_sum;

__global__ void mde_zero_kernel() {
    g_mde_sum = 0.0;
}

// Grid-stride over edges: one int2 edge load, two float4 gathers from X
// (16 MB table, fully L2-resident), one weight load, FMA chain, then
// warp+block reduce and one double atomicAdd per block.
__global__ void __launch_bounds__(256)
mde_kernel(const float4* __restrict__ X,
           const int2* __restrict__ edges,
           const float* __restrict__ w,
           int p) {
    float acc = 0.0f;
    int stride = gridDim.x * blockDim.x;
    for (int k = blockIdx.x * blockDim.x + threadIdx.x; k < p; k += stride) {
        int2 e = __ldg(&edges[k]);
        float4 a = __ldg(&X[e.x]);
        float4 b = __ldg(&X[e.y]);
        float dx = a.x - b.x;
        float dy = a.y - b.y;
        float dz = a.z - b.z;
        float dw = a.w - b.w;
        float d2 = dx * dx + dy * dy + dz * dz + dw * dw;
        acc = fmaf(__ldg(&w[k]), d2, acc);
    }

    // Warp reduction
    #pragma unroll
    for (int off = 16; off > 0; off >>= 1)
        acc += __shfl_down_sync(0xffffffffu, acc, off);

    // Block reduction via shared memory
    __shared__ float warp_sums[8];  // 256 threads = 8 warps
    int lane = threadIdx.x & 31;
    int wid  = threadIdx.x >> 5;
    if (lane == 0) warp_sums[wid] = acc;
    __syncthreads();

    if (wid == 0) {
        float v = (lane < 8) ? warp_sums[lane] : 0.0f;
        #pragma unroll
        for (int off = 4; off > 0; off >>= 1)
            v += __shfl_down_sync(0xffffffffu, v, off);
        if (lane == 0)
            atomicAdd(&g_mde_sum, (double)v);
    }
}

__global__ void mde_finalize_kernel(float* __restrict__ out, double inv_p) {
    out[0] = (float)(g_mde_sum * inv_p);
}

extern "C" void kernel_launch(void* const* d_in, const int* in_sizes, int n_in,
                              void* d_out, int out_size) {
    // Inputs: X (f32, 1M x 4), edges (int32, 10M x 2 — JAX x64 disabled!), weights (f32, 10M)
    const float4* X     = (const float4*)d_in[0];
    const int2*   edges = (const int2*)d_in[1];
    const float*  w     = (const float*)d_in[2];
    float*        out   = (float*)d_out;

    int p = in_sizes[2];  // number of edges = weights element count

    mde_zero_kernel<<<1, 1>>>();

    const int threads = 256;
    const int edges_per_thread = 8;
    long long want = ((long long)p + (long long)threads * edges_per_thread - 1) /
                     ((long long)threads * edges_per_thread);
    int blocks = (int)((want < 1) ? 1 : (want > 1048576 ? 1048576 : want));
    mde_kernel<<<blocks, threads>>>(X, edges, w, p);

    mde_finalize_kernel<<<1, 1>>>(out, 1.0 / (double)p);
}

// round 3
// speedup vs baseline: 1.0195x; 1.0195x over previous
#include <cuda_runtime.h>
#include <cstdint>

// Scratch (no allocations allowed): per-block partials + completion ticket.
#define MAX_BLOCKS 2048
__device__ float g_partials[MAX_BLOCKS];
__device__ unsigned int g_ticket = 0;   // always 0 between calls (last block resets)

// Single fused kernel:
//  - grid-stride over edge PAIRS (int4 = 2 edges, float2 = 2 weights), streams
//    marked evict-first (__ldcs) so the 16 MB X table stays L2-resident,
//  - 4 independent float4 gathers per iteration for MLP,
//  - block reduce -> g_partials[blockIdx], last-done block reduces partials,
//    writes the mean, and resets the ticket (deterministic across replays).
__global__ void __launch_bounds__(256)
mde_fused_kernel(const float4* __restrict__ X,
                 const int4* __restrict__ epairs,   // 2 edges per element
                 const float2* __restrict__ wpairs, // 2 weights per element
                 int npairs,
                 const int2* __restrict__ etail,    // leftover single edge view
                 const float* __restrict__ wtail,
                 int p,                             // total edges
                 float* __restrict__ out,
                 float inv_p) {
    float acc = 0.0f;
    int stride = gridDim.x * blockDim.x;
    int tid = blockIdx.x * blockDim.x + threadIdx.x;

    for (int k = tid; k < npairs; k += stride) {
        int4   e = __ldcs(&epairs[k]);
        float2 w = __ldcs(&wpairs[k]);
        float4 a0 = __ldg(&X[e.x]);
        float4 b0 = __ldg(&X[e.y]);
        float4 a1 = __ldg(&X[e.z]);
        float4 b1 = __ldg(&X[e.w]);
        float dx0 = a0.x - b0.x, dy0 = a0.y - b0.y, dz0 = a0.z - b0.z, dw0 = a0.w - b0.w;
        float dx1 = a1.x - b1.x, dy1 = a1.y - b1.y, dz1 = a1.z - b1.z, dw1 = a1.w - b1.w;
        float d20 = dx0 * dx0 + dy0 * dy0 + dz0 * dz0 + dw0 * dw0;
        float d21 = dx1 * dx1 + dy1 * dy1 + dz1 * dz1 + dw1 * dw1;
        acc = fmaf(w.x, d20, acc);
        acc = fmaf(w.y, d21, acc);
    }

    // Tail edges (p odd): handled by first few threads.
    int tail_base = npairs * 2;
    for (int k = tail_base + tid; k < p; k += stride) {
        int2 e = __ldg(&etail[k]);
        float4 a = __ldg(&X[e.x]);
        float4 b = __ldg(&X[e.y]);
        float dx = a.x - b.x, dy = a.y - b.y, dz = a.z - b.z, dw = a.w - b.w;
        acc = fmaf(__ldg(&wtail[k]), dx * dx + dy * dy + dz * dz + dw * dw, acc);
    }

    // Warp reduction
    #pragma unroll
    for (int off = 16; off > 0; off >>= 1)
        acc += __shfl_down_sync(0xffffffffu, acc, off);

    __shared__ float warp_sums[8];
    int lane = threadIdx.x & 31;
    int wid  = threadIdx.x >> 5;
    if (lane == 0) warp_sums[wid] = acc;
    __syncthreads();

    __shared__ bool is_last;
    if (wid == 0) {
        float v = (lane < 8) ? warp_sums[lane] : 0.0f;
        #pragma unroll
        for (int off = 4; off > 0; off >>= 1)
            v += __shfl_down_sync(0xffffffffu, v, off);
        if (lane == 0) {
            g_partials[blockIdx.x] = v;
            __threadfence();
            unsigned int done = atomicInc(&g_ticket, gridDim.x - 1);
            is_last = (done == gridDim.x - 1);  // atomicInc wraps to 0 on last -> ticket reset
        }
    }
    __syncthreads();

    // Last block reduces the per-block partials and writes the mean.
    if (is_last) {
        double s = 0.0;
        for (int i = threadIdx.x; i < gridDim.x; i += blockDim.x)
            s += (double)g_partials[i];
        // double block reduction via shared
        __shared__ double dsums[8];
        #pragma unroll
        for (int off = 16; off > 0; off >>= 1)
            s += __shfl_down_sync(0xffffffffu, s, off);
        if (lane == 0) dsums[wid] = s;
        __syncthreads();
        if (wid == 0) {
            double t = (lane < 8) ? dsums[lane] : 0.0;
            #pragma unroll
            for (int off = 4; off > 0; off >>= 1)
                t += __shfl_down_sync(0xffffffffu, t, off);
            if (lane == 0)
                out[0] = (float)(t * (double)inv_p);
        }
    }
}

extern "C" void kernel_launch(void* const* d_in, const int* in_sizes, int n_in,
                              void* d_out, int out_size) {
    // Inputs: X (f32, 1M x 4), edges (int32, 10M x 2), weights (f32, 10M)
    const float4* X     = (const float4*)d_in[0];
    const int*    edges = (const int*)d_in[1];
    const float*  w     = (const float*)d_in[2];
    float*        out   = (float*)d_out;

    int p = in_sizes[2];
    int npairs = p / 2;

    const int threads = 256;
    int blocks = 1184;  // 148 SMs * 8 blocks
    if (blocks > MAX_BLOCKS) blocks = MAX_BLOCKS;

    mde_fused_kernel<<<blocks, threads>>>(
        X,
        (const int4*)edges, (const float2*)w, npairs,
        (const int2*)edges, w, p,
        out, 1.0f / (float)p);
}